// round 5
// baseline (speedup 1.0000x reference)
#include <cuda_runtime.h>
#include <vector>
#include <algorithm>
#include <cstring>

// ---------------- problem constants ----------------
#define B_    8
#define S_    4096
#define D_    512
#define QT    128        // queries per block
#define NTH   256        // threads per block
#define NDEP  8
#define NJP   132        // padded union key count (real nu = 129)
#define RP    132        // padded row length (floats) for smem tiles
#define KC    32         // k-chunk for score GEMM

// smem float offsets
#define DBUF_STRIDE (2 * KC * RP)        // 8448 floats per (Q,K) buffer pair
#define VS_OFF      (NJP * RP)           // 17424
#define VS_STRIDE   (32 * RP)            // 4224
#define SMEM_FLOATS (VS_OFF + 2 * VS_STRIDE)  // 25872 -> 103488 B

// column swizzle: chunk (jg = j>>3, h = (j>>2)&1) stored at slot jg + 16*h
// float index of element j inside a row: ((j>>3) + ((j>>2)&1)*16)*4 + (j&3)
#define SWZ(j) ((((j) >> 3) + (((j) >> 2) & 1) * 16) * 4 + ((j) & 3))

// ---------------- host-side Cantor tables ----------------
struct CTab { int idx[NJP]; int bnd[NDEP + 1]; int nu; };
static CTab g_tab;

static bool build_tables() {
    std::vector<std::vector<long long>> idxd;
    auto to_idx = [](const std::vector<double>& p) {
        std::vector<long long> v;
        v.reserve(p.size());
        for (double x : p) v.push_back((long long)(x * 4095.0));
        std::sort(v.begin(), v.end());
        v.erase(std::unique(v.begin(), v.end()), v.end());
        return v;
    };
    std::vector<double> prev = {0.0, 1.0};
    idxd.push_back(to_idx(prev));
    for (int d = 1; d < NDEP; ++d) {
        std::vector<double> nw;
        nw.reserve(prev.size() * 2);
        for (size_t i = 0; i + 1 < prev.size(); ++i) {
            double left  = prev[i];
            double right = prev[i + 1];
            double third = (right - left) / 3.0;
            nw.push_back(left);
            nw.push_back(left + third);
        }
        nw.push_back(prev.back());
        prev.swap(nw);
        idxd.push_back(to_idx(prev));
    }
    const std::vector<long long>& uni = idxd[NDEP - 1];
    int nu = (int)uni.size();
    if (nu > NJP) nu = NJP;
    std::vector<std::pair<int, long long>> keys;
    for (int j = 0; j < nu; ++j) {
        int dm = NDEP - 1;
        for (int d = 0; d < NDEP; ++d)
            if (std::binary_search(idxd[d].begin(), idxd[d].end(), uni[j])) { dm = d; break; }
        keys.push_back({dm, uni[j]});
    }
    std::sort(keys.begin(), keys.end());
    for (int j = 0; j < nu; ++j) g_tab.idx[j] = (int)keys[j].second;
    for (int j = nu; j < NJP; ++j) g_tab.idx[j] = g_tab.idx[0];
    for (int d = 0; d <= NDEP; ++d) {
        int c = 0;
        for (auto& kv : keys) if (kv.first < d) ++c;
        g_tab.bnd[d] = c;
    }
    g_tab.nu = nu;
    return true;
}
static bool g_built = build_tables();

// ---------------- packed f32x2 helpers ----------------
typedef unsigned long long ull;

__device__ __forceinline__ ull dup2(float x) {
    ull r;
    asm("mov.b64 %0, {%1, %1};" : "=l"(r) : "r"(__float_as_uint(x)));
    return r;
}
__device__ __forceinline__ void fma2(ull& d, ull a, ull b) {
    asm("fma.rn.f32x2 %0, %1, %2, %0;" : "+l"(d) : "l"(a), "l"(b));
}
__device__ __forceinline__ float2 u2f(ull v) {
    float2 f;
    memcpy(&f, &v, 8);
    return f;
}

// ---------------- kernel ----------------
__global__ __launch_bounds__(NTH, 2)
void ufa4_kernel(const float* __restrict__ Q, const float* __restrict__ K,
                 const float* __restrict__ V, const float* __restrict__ SW,
                 const float* __restrict__ ST, float* __restrict__ O, CTab tab)
{
    extern __shared__ float sm[];
    float* cs = sm;                    // NJP x RP  [j][q]; rows 0..127 double as phase-A dbuf

    __shared__ int   si[NJP];
    __shared__ float wv[NDEP];

    const int tid   = threadIdx.x;
    const int b     = blockIdx.y;
    const int q0blk = blockIdx.x * QT;
    const int nu    = tab.nu;
    const float inv_scale = 0.04419417382415922f;  // 1/sqrt(512)

    const int qg  = tid >> 4;          // 0..15
    const int jg  = tid & 15;          // 0..15
    const int qq0 = qg * 8;
    const int jj0 = jg * 8;

    const int lane = tid & 31;
    const int w    = tid >> 5;

    for (int i = tid; i < NJP; i += NTH) si[i] = tab.idx[i];
    if (tid == 0) {
        float tmp = ST[0];
        float vvv[NDEP];
        float m = -1e30f;
        #pragma unroll
        for (int d = 0; d < NDEP; ++d) { vvv[d] = SW[d] / tmp; m = fmaxf(m, vvv[d]); }
        float s = 0.f;
        #pragma unroll
        for (int d = 0; d < NDEP; ++d) { vvv[d] = __expf(vvv[d] - m); s += vvv[d]; }
        #pragma unroll
        for (int d = 0; d < NDEP; ++d) wv[d] = vvv[d] / s;
    }
    __syncthreads();

    // ---- score column j = 128 (outside the 128x128 GEMM); writes cs row 128 ----
    {
        int q = tid >> 1, h = tid & 1;
        const float4* qr4 = (const float4*)(Q + ((size_t)b * S_ + q0blk + q) * D_ + h * 256);
        const float4* kr4 = (const float4*)(K + ((size_t)b * S_ + si[128]) * D_ + h * 256);
        float s = 0.f;
        #pragma unroll 8
        for (int i = 0; i < 64; ++i) {
            float4 a = qr4[i];
            float4 c = kr4[i];
            s = fmaf(a.x, c.x, s);
            s = fmaf(a.y, c.y, s);
            s = fmaf(a.z, c.z, s);
            s = fmaf(a.w, c.w, s);
        }
        s += __shfl_xor_sync(0xffffffffu, s, 1);
        if (h == 0) cs[128 * RP + q] = s * inv_scale;
    }

    // ---- phase A: score GEMM  S[128q x 128j] = Q . K^T  (double-buffered) ----
    ull acc[4][8];
    #pragma unroll
    for (int p = 0; p < 4; ++p)
        #pragma unroll
        for (int i = 0; i < 8; ++i)
            acc[p][i] = 0ull;

    // fill chunk ck into buffer s. lane <-> column, warp <-> k-quad:
    // Q stores conflict-free; K stores 2-way (swizzled cols).
    auto fillA = [&](int ck, int s) {
        float* Qb = sm + s * DBUF_STRIDE;
        float* Kb = Qb + KC * RP;
        #pragma unroll
        for (int rr = 0; rr < 4; ++rr) {
            const int q = lane + 32 * rr;
            float4 v = *(const float4*)(Q + ((size_t)b * S_ + q0blk + q) * D_ + ck * KC + w * 4);
            Qb[(w * 4 + 0) * RP + q] = v.x;
            Qb[(w * 4 + 1) * RP + q] = v.y;
            Qb[(w * 4 + 2) * RP + q] = v.z;
            Qb[(w * 4 + 3) * RP + q] = v.w;
            float4 u = *(const float4*)(K + ((size_t)b * S_ + si[q]) * D_ + ck * KC + w * 4);
            const int sc_ = SWZ(q);
            Kb[(w * 4 + 0) * RP + sc_] = u.x;
            Kb[(w * 4 + 1) * RP + sc_] = u.y;
            Kb[(w * 4 + 2) * RP + sc_] = u.z;
            Kb[(w * 4 + 3) * RP + sc_] = u.w;
        }
    };

    fillA(0, 0);
    __syncthreads();

    #pragma unroll 1
    for (int ck = 0; ck < D_ / KC; ++ck) {
        const int s = ck & 1;
        if (ck < D_ / KC - 1) fillA(ck + 1, s ^ 1);

        const float* Qb = sm + s * DBUF_STRIDE;
        const float* Kb = Qb + KC * RP;
        #pragma unroll 4
        for (int k = 0; k < KC; ++k) {
            const float* kr = Kb + k * RP;
            float4 ka = *(const float4*)(kr + jg * 4);          // slots jg      (2-wf)
            float4 kb = *(const float4*)(kr + (jg + 16) * 4);   // slots jg+16   (2-wf)
            ull kd0 = dup2(ka.x), kd1 = dup2(ka.y), kd2 = dup2(ka.z), kd3 = dup2(ka.w);
            ull kd4 = dup2(kb.x), kd5 = dup2(kb.y), kd6 = dup2(kb.z), kd7 = dup2(kb.w);
            const float* qrp = Qb + k * RP + qq0;
            ulonglong2 qA = *(const ulonglong2*)(qrp);
            ulonglong2 qB = *(const ulonglong2*)(qrp + 4);
            ull qp0 = qA.x, qp1 = qA.y, qp2 = qB.x, qp3 = qB.y;
            fma2(acc[0][0], qp0, kd0); fma2(acc[0][1], qp0, kd1);
            fma2(acc[0][2], qp0, kd2); fma2(acc[0][3], qp0, kd3);
            fma2(acc[0][4], qp0, kd4); fma2(acc[0][5], qp0, kd5);
            fma2(acc[0][6], qp0, kd6); fma2(acc[0][7], qp0, kd7);
            fma2(acc[1][0], qp1, kd0); fma2(acc[1][1], qp1, kd1);
            fma2(acc[1][2], qp1, kd2); fma2(acc[1][3], qp1, kd3);
            fma2(acc[1][4], qp1, kd4); fma2(acc[1][5], qp1, kd5);
            fma2(acc[1][6], qp1, kd6); fma2(acc[1][7], qp1, kd7);
            fma2(acc[2][0], qp2, kd0); fma2(acc[2][1], qp2, kd1);
            fma2(acc[2][2], qp2, kd2); fma2(acc[2][3], qp2, kd3);
            fma2(acc[2][4], qp2, kd4); fma2(acc[2][5], qp2, kd5);
            fma2(acc[2][6], qp2, kd6); fma2(acc[2][7], qp2, kd7);
            fma2(acc[3][0], qp3, kd0); fma2(acc[3][1], qp3, kd1);
            fma2(acc[3][2], qp3, kd2); fma2(acc[3][3], qp3, kd3);
            fma2(acc[3][4], qp3, kd4); fma2(acc[3][5], qp3, kd5);
            fma2(acc[3][6], qp3, kd6); fma2(acc[3][7], qp3, kd7);
        }
        __syncthreads();
    }

    // writeback scores: acc[p][i] holds (q = qq0+2p(+1), j = jj0 + chunk-order i)
    // chunk order i: elements j = jj0 + (i<4 ? i : 4 + (i-4)) — i maps 1:1 to j=jj0+i
    // because ka covered j = jj0..jj0+3 (slot jg) and kb j = jj0+4..jj0+7 (slot jg+16).
    #pragma unroll
    for (int p = 0; p < 4; ++p)
        #pragma unroll
        for (int i = 0; i < 8; ++i) {
            float2 e = u2f(acc[p][i]);
            float2 o = make_float2(e.x * inv_scale, e.y * inv_scale);
            *(float2*)(cs + (jj0 + i) * RP + qq0 + 2 * p) = o;
        }
    __syncthreads();

    // ---- phase 3: fused nested softmax -> coefficient per key ----
    if (tid < QT) {
        const int q = tid;
        float m = -1e30f;
        for (int j = 0; j < nu; ++j) m = fmaxf(m, cs[j * RP + q]);
        float gs[NDEP];
        #pragma unroll
        for (int d = 0; d < NDEP; ++d) {
            float s = 0.f;
            for (int j = tab.bnd[d]; j < tab.bnd[d + 1]; ++j) {
                float e = __expf(cs[j * RP + q] - m);
                cs[j * RP + q] = e;
                s += e;
            }
            gs[d] = s;
        }
        float Z = 0.f, sa[NDEP];
        #pragma unroll
        for (int d = 0; d < NDEP; ++d) { Z += gs[d]; sa[d] = __fdividef(wv[d], Z); }
        float ss = 0.f;
        #pragma unroll
        for (int d = NDEP - 1; d >= 0; --d) { ss += sa[d]; sa[d] = ss; }
        #pragma unroll
        for (int d = 0; d < NDEP; ++d)
            for (int j = tab.bnd[d]; j < tab.bnd[d + 1]; ++j)
                cs[j * RP + q] *= sa[d];
    }

    // ---- phase 4: O[128q x 512d] = C . V ; 16 tiles (4 dc x 4 jt), double-buffered;
    //      key j=128 folded into a per-dc register epilogue ----
    const int dd0 = jj0;

    auto fillV = [&](int t, int s) {
        const int dc = t >> 2, jt = (t & 3) * 32;
        float* Vb = sm + VS_OFF + s * VS_STRIDE;
        const int slot = (lane >> 1) + (lane & 1) * 16;  // swizzled col slot for d-chunk lane*4
        #pragma unroll
        for (int rr = 0; rr < 4; ++rr) {
            int jr = w + 8 * rr;
            float4 v = *(const float4*)(V + ((size_t)b * S_ + si[jt + jr]) * D_ + dc * 128 + lane * 4);
            *(float4*)(Vb + jr * RP + slot * 4) = v;
        }
    };

    ull av[4][8];
    const int si128 = si[128];

    fillV(0, 0);
    __syncthreads();

    #pragma unroll 1
    for (int t = 0; t < 16; ++t) {
        const int s  = t & 1;
        const int dc = t >> 2;
        if (t < 15) fillV(t + 1, s ^ 1);

        if ((t & 3) == 0) {
            #pragma unroll
            for (int p = 0; p < 4; ++p)
                #pragma unroll
                for (int i = 0; i < 8; ++i)
                    av[p][i] = 0ull;
        }

        const float* Vb = sm + VS_OFF + s * VS_STRIDE;
        const int jt = (t & 3) * 32;
        #pragma unroll 4
        for (int jj = 0; jj < 32; ++jj) {
            const float* vr = Vb + jj * RP;
            float4 va = *(const float4*)(vr + jg * 4);          // d = dd0..dd0+3
            float4 vb = *(const float4*)(vr + (jg + 16) * 4);   // d = dd0+4..dd0+7
            ull vd0 = dup2(va.x), vd1 = dup2(va.y), vd2 = dup2(va.z), vd3 = dup2(va.w);
            ull vd4 = dup2(vb.x), vd5 = dup2(vb.y), vd6 = dup2(vb.z), vd7 = dup2(vb.w);
            const float* crp = cs + (jt + jj) * RP + qq0;
            ulonglong2 cA = *(const ulonglong2*)(crp);
            ulonglong2 cB = *(const ulonglong2*)(crp + 4);
            ull cp0 = cA.x, cp1 = cA.y, cp2 = cB.x, cp3 = cB.y;
            fma2(av[0][0], cp0, vd0); fma2(av[0][1], cp0, vd1);
            fma2(av[0][2], cp0, vd2); fma2(av[0][3], cp0, vd3);
            fma2(av[0][4], cp0, vd4); fma2(av[0][5], cp0, vd5);
            fma2(av[0][6], cp0, vd6); fma2(av[0][7], cp0, vd7);
            fma2(av[1][0], cp1, vd0); fma2(av[1][1], cp1, vd1);
            fma2(av[1][2], cp1, vd2); fma2(av[1][3], cp1, vd3);
            fma2(av[1][4], cp1, vd4); fma2(av[1][5], cp1, vd5);
            fma2(av[1][6], cp1, vd6); fma2(av[1][7], cp1, vd7);
            fma2(av[2][0], cp2, vd0); fma2(av[2][1], cp2, vd1);
            fma2(av[2][2], cp2, vd2); fma2(av[2][3], cp2, vd3);
            fma2(av[2][4], cp2, vd4); fma2(av[2][5], cp2, vd5);
            fma2(av[2][6], cp2, vd6); fma2(av[2][7], cp2, vd7);
            fma2(av[3][0], cp3, vd0); fma2(av[3][1], cp3, vd1);
            fma2(av[3][2], cp3, vd2); fma2(av[3][3], cp3, vd3);
            fma2(av[3][4], cp3, vd4); fma2(av[3][5], cp3, vd5);
            fma2(av[3][6], cp3, vd6); fma2(av[3][7], cp3, vd7);
        }

        if ((t & 3) == 3) {
            // epilogue: key j=128 contribution for this dc chunk (global broadcast loads)
            const float* v128 = V + ((size_t)b * S_ + si128) * D_ + dc * 128 + dd0;
            float4 va = *(const float4*)v128;
            float4 vb = *(const float4*)(v128 + 4);
            ull vd0 = dup2(va.x), vd1 = dup2(va.y), vd2 = dup2(va.z), vd3 = dup2(va.w);
            ull vd4 = dup2(vb.x), vd5 = dup2(vb.y), vd6 = dup2(vb.z), vd7 = dup2(vb.w);
            const float* crp = cs + 128 * RP + qq0;
            ulonglong2 cA = *(const ulonglong2*)(crp);
            ulonglong2 cB = *(const ulonglong2*)(crp + 4);
            ull cp0 = cA.x, cp1 = cA.y, cp2 = cB.x, cp3 = cB.y;
            fma2(av[0][0], cp0, vd0); fma2(av[0][1], cp0, vd1);
            fma2(av[0][2], cp0, vd2); fma2(av[0][3], cp0, vd3);
            fma2(av[0][4], cp0, vd4); fma2(av[0][5], cp0, vd5);
            fma2(av[0][6], cp0, vd6); fma2(av[0][7], cp0, vd7);
            fma2(av[1][0], cp1, vd0); fma2(av[1][1], cp1, vd1);
            fma2(av[1][2], cp1, vd2); fma2(av[1][3], cp1, vd3);
            fma2(av[1][4], cp1, vd4); fma2(av[1][5], cp1, vd5);
            fma2(av[1][6], cp1, vd6); fma2(av[1][7], cp1, vd7);
            fma2(av[2][0], cp2, vd0); fma2(av[2][1], cp2, vd1);
            fma2(av[2][2], cp2, vd2); fma2(av[2][3], cp2, vd3);
            fma2(av[2][4], cp2, vd4); fma2(av[2][5], cp2, vd5);
            fma2(av[2][6], cp2, vd6); fma2(av[2][7], cp2, vd7);
            fma2(av[3][0], cp3, vd0); fma2(av[3][1], cp3, vd1);
            fma2(av[3][2], cp3, vd2); fma2(av[3][3], cp3, vd3);
            fma2(av[3][4], cp3, vd4); fma2(av[3][5], cp3, vd5);
            fma2(av[3][6], cp3, vd6); fma2(av[3][7], cp3, vd7);

            // write O chunk
            #pragma unroll
            for (int p = 0; p < 4; ++p) {
                float2 e0 = u2f(av[p][0]), e1 = u2f(av[p][1]), e2 = u2f(av[p][2]), e3 = u2f(av[p][3]);
                float2 e4 = u2f(av[p][4]), e5 = u2f(av[p][5]), e6 = u2f(av[p][6]), e7 = u2f(av[p][7]);
                size_t base = ((size_t)b * S_ + q0blk + qq0 + 2 * p) * D_ + dc * 128 + dd0;
                *(float4*)(O + base + 0) = make_float4(e0.x, e1.x, e2.x, e3.x);
                *(float4*)(O + base + 4) = make_float4(e4.x, e5.x, e6.x, e7.x);
                *(float4*)(O + base + D_ + 0) = make_float4(e0.y, e1.y, e2.y, e3.y);
                *(float4*)(O + base + D_ + 4) = make_float4(e4.y, e5.y, e6.y, e7.y);
            }
        }
        __syncthreads();
    }
}

// ---------------- launch ----------------
extern "C" void kernel_launch(void* const* d_in, const int* in_sizes, int n_in,
                              void* d_out, int out_size)
{
    const float* Q  = (const float*)d_in[0];
    const float* K  = (const float*)d_in[1];
    const float* V  = (const float*)d_in[2];
    // d_in[3] = t (unused by the reference)
    const float* SW = (const float*)d_in[4];
    const float* ST = (const float*)d_in[5];
    float* O = (float*)d_out;

    const int smem_bytes = SMEM_FLOATS * (int)sizeof(float);  // 103488
    cudaFuncSetAttribute(ufa4_kernel, cudaFuncAttributeMaxDynamicSharedMemorySize, smem_bytes);

    dim3 grid(S_ / QT, B_);
    ufa4_kernel<<<grid, NTH, smem_bytes>>>(Q, K, V, SW, ST, O, g_tab);
}

// round 8
// speedup vs baseline: 1.4831x; 1.4831x over previous
#include <cuda_runtime.h>
#include <cuda_bf16.h>
#include <cstdint>
#include <vector>
#include <algorithm>

// ---------------- problem constants ----------------
#define B_    8
#define S_    4096
#define D_    512
#define QT    128
#define NTH   256
#define NDEP  8

// smem byte offsets (dynamic smem base AB)
// phase A tiles (128 rows x 128B, SW-swizzled) overlay the C region:
#define QHI_OFF 0
#define QLO_OFF 16384
#define KHI_OFF 32768
#define KLO_OFF 49152
// phase B: C split tiles [128 q][136 bf16] pitch 272B; Vt tiles [64 d][136 bf16]
#define CHI_OFF 0
#define CLO_OFF 34816
#define VHI_OFF 69632
#define VLO_OFF 87040
#define DYN_BYTES 104448
#define CPITCH 272

// ---------------- host-side Cantor table (keys sorted by (dmin, idx)) ----------------
struct CTab { int idx[129]; };
static CTab g_tab;

static bool build_tables() {
    std::vector<std::vector<long long>> idxd;
    auto to_idx = [](const std::vector<double>& p) {
        std::vector<long long> v;
        for (double x : p) v.push_back((long long)(x * 4095.0));
        std::sort(v.begin(), v.end());
        v.erase(std::unique(v.begin(), v.end()), v.end());
        return v;
    };
    std::vector<double> prev = {0.0, 1.0};
    idxd.push_back(to_idx(prev));
    for (int d = 1; d < NDEP; ++d) {
        std::vector<double> nw;
        for (size_t i = 0; i + 1 < prev.size(); ++i) {
            double left = prev[i], right = prev[i + 1];
            double third = (right - left) / 3.0;
            nw.push_back(left);
            nw.push_back(left + third);
        }
        nw.push_back(prev.back());
        prev.swap(nw);
        idxd.push_back(to_idx(prev));
    }
    const std::vector<long long>& uni = idxd[NDEP - 1];   // 129 keys (nested union)
    int nu = (int)uni.size();
    std::vector<std::pair<int, long long>> keys;
    for (int j = 0; j < nu; ++j) {
        int dm = NDEP - 1;
        for (int d = 0; d < NDEP; ++d)
            if (std::binary_search(idxd[d].begin(), idxd[d].end(), uni[j])) { dm = d; break; }
        keys.push_back({dm, uni[j]});
    }
    std::sort(keys.begin(), keys.end());
    for (int j = 0; j < nu && j < 129; ++j) g_tab.idx[j] = (int)keys[j].second;
    return true;
}
static bool g_built = build_tables();
// sorted-slot depth groups: bnd = {0,2,3,5,9,17,33,65,129}

// ---------------- helpers ----------------
__device__ __forceinline__ uint32_t s2u(const void* p) {
    uint32_t a;
    asm("{ .reg .u64 t; cvta.to.shared.u64 t, %1; cvt.u32.u64 %0, t; }" : "=r"(a) : "l"(p));
    return a;
}

#define LDSM4(r0, r1, r2, r3, addr) \
    asm volatile("ldmatrix.sync.aligned.m8n8.x4.shared.b16 {%0,%1,%2,%3}, [%4];" \
                 : "=r"(r0), "=r"(r1), "=r"(r2), "=r"(r3) : "r"(addr))

#define MMA(d, a0, a1, a2, a3, b0, b1) \
    asm volatile("mma.sync.aligned.m16n8k16.row.col.f32.bf16.bf16.f32 " \
                 "{%0,%1,%2,%3}, {%4,%5,%6,%7}, {%8,%9}, {%0,%1,%2,%3};" \
                 : "+f"((d)[0]), "+f"((d)[1]), "+f"((d)[2]), "+f"((d)[3]) \
                 : "r"(a0), "r"(a1), "r"(a2), "r"(a3), "r"(b0), "r"(b1))

// split x -> hi (round-to-nearest bf16) + lo (rounded bf16 of exact remainder); pack 2
__device__ __forceinline__ void split2(float c0, float c1, uint32_t& hi, uint32_t& lo) {
    asm("cvt.rn.bf16x2.f32 %0, %1, %2;" : "=r"(hi) : "f"(c1), "f"(c0));
    float h0 = __uint_as_float(hi << 16);
    float h1 = __uint_as_float(hi & 0xFFFF0000u);
    float l0 = c0 - h0;   // exact in fp32
    float l1 = c1 - h1;
    asm("cvt.rn.bf16x2.f32 %0, %1, %2;" : "=r"(lo) : "f"(l1), "f"(l0));
}
__device__ __forceinline__ void split_store4(char* hiB, char* loB, uint32_t off, float4 v) {
    uint32_t h01, l01, h23, l23;
    split2(v.x, v.y, h01, l01);
    split2(v.z, v.w, h23, l23);
    *(uint2*)(hiB + off) = make_uint2(h01, h23);
    *(uint2*)(loB + off) = make_uint2(l01, l23);
}

// depth-group accumulation (nt literal after unroll -> all indices static)
__device__ __forceinline__ void gacc(int nt, float* g, float e0, float e1, int t) {
    if (nt == 0) {
        g[0] += (t == 0) ? (e0 + e1) : 0.f;
        g[1] += (t == 1) ? e0 : 0.f;
        g[2] += (t == 1) ? e1 : ((t == 2) ? e0 : 0.f);
        g[3] += (t == 2) ? e1 : ((t == 3) ? (e0 + e1) : 0.f);
    } else if (nt == 1) {
        g[3] += (t == 0) ? e0 : 0.f;
        g[4] += (t == 0) ? e1 : (e0 + e1);
    } else if (nt == 2) {
        g[4] += (t == 0) ? e0 : 0.f;
        g[5] += (t == 0) ? e1 : (e0 + e1);
    } else if (nt == 3) {
        g[5] += e0 + e1;
    } else if (nt == 4) {
        g[5] += (t == 0) ? e0 : 0.f;
        g[6] += (t == 0) ? e1 : (e0 + e1);
    } else if (nt <= 7) {
        g[6] += e0 + e1;
    } else if (nt == 8) {
        g[6] += (t == 0) ? e0 : 0.f;
        g[7] += (t == 0) ? e1 : (e0 + e1);
    } else {
        g[7] += e0 + e1;
    }
}
__device__ __forceinline__ float2 samul(int nt, const float* sa, int t) {
    float m0, m1;
    if (nt == 0) {
        m0 = (t == 0) ? sa[0] : (t == 1) ? sa[1] : (t == 2) ? sa[2] : sa[3];
        m1 = (t == 0) ? sa[0] : (t == 1) ? sa[2] : sa[3];
    } else if (nt == 1) { m0 = (t == 0) ? sa[3] : sa[4]; m1 = sa[4]; }
    else if (nt == 2)   { m0 = (t == 0) ? sa[4] : sa[5]; m1 = sa[5]; }
    else if (nt == 3)   { m0 = sa[5]; m1 = sa[5]; }
    else if (nt == 4)   { m0 = (t == 0) ? sa[5] : sa[6]; m1 = sa[6]; }
    else if (nt <= 7)   { m0 = sa[6]; m1 = sa[6]; }
    else if (nt == 8)   { m0 = (t == 0) ? sa[6] : sa[7]; m1 = sa[7]; }
    else                { m0 = sa[7]; m1 = sa[7]; }
    return make_float2(m0, m1);
}

// ---------------- kernel ----------------
__global__ __launch_bounds__(NTH, 2)
void ufa7_kernel(const float* __restrict__ Q, const float* __restrict__ K,
                 const float* __restrict__ V, const float* __restrict__ SW,
                 const float* __restrict__ ST, float* __restrict__ O, CTab tab)
{
    extern __shared__ char AB[];
    const uint32_t ab = s2u(AB);

    __shared__ int   si[129];
    __shared__ float wv[NDEP];
    __shared__ float s128s[128];
    __shared__ float c128s[128];

    const int tid  = threadIdx.x;
    const int w    = tid >> 5;
    const int lane = tid & 31;
    const int b    = blockIdx.y;
    const int q0   = blockIdx.x * QT;
    const float inv_scale = 0.04419417382415922f;  // 1/sqrt(512)

    const int lr = lane & 15;   // ldmatrix row-within-16
    const int lc = lane >> 4;   // ldmatrix k-half
    const int t4 = lane & 3;
    const int rq = lane >> 2;   // fragment row 0..7

    for (int i = tid; i < 129; i += NTH) si[i] = tab.idx[i];
    if (tid == 0) {
        float tmp = ST[0];
        float vvv[NDEP];
        float m = -1e30f;
        #pragma unroll
        for (int d = 0; d < NDEP; ++d) { vvv[d] = SW[d] / tmp; m = fmaxf(m, vvv[d]); }
        float s = 0.f;
        #pragma unroll
        for (int d = 0; d < NDEP; ++d) { vvv[d] = __expf(vvv[d] - m); s += vvv[d]; }
        #pragma unroll
        for (int d = 0; d < NDEP; ++d) wv[d] = vvv[d] / s;
    }
    __syncthreads();

    // ---- raw score column j = 128 ----
    {
        int q = tid >> 1, h = tid & 1;
        const float4* qr = (const float4*)(Q + ((size_t)b * S_ + q0 + q) * D_ + h * 256);
        const float4* kr = (const float4*)(K + ((size_t)b * S_ + si[128]) * D_ + h * 256);
        float s = 0.f;
        #pragma unroll 8
        for (int i = 0; i < 64; ++i) {
            float4 a = qr[i], c = kr[i];
            s = fmaf(a.x, c.x, s); s = fmaf(a.y, c.y, s);
            s = fmaf(a.z, c.z, s); s = fmaf(a.w, c.w, s);
        }
        s += __shfl_xor_sync(0xffffffffu, s, 1);
        if (h == 0) s128s[q] = s;   // RAW (scaled later in softmax)
    }

    // ================= phase A: S = Q.K^T (raw), split-bf16 mma =================
    float acc[16][4];
    #pragma unroll
    for (int nt = 0; nt < 16; ++nt)
        #pragma unroll
        for (int i = 0; i < 4; ++i)
            acc[nt][i] = 0.f;

    const int frow = tid >> 1;
    const int fkh  = (tid & 1) * 32;

    #pragma unroll 1
    for (int ck = 0; ck < 8; ++ck) {
        // fill Q/K split tiles for this 64-dim chunk (128B rows, XOR-swizzled 16B chunks)
        {
            const float4* Qr = (const float4*)(Q + ((size_t)b * S_ + q0 + frow) * D_ + ck * 64 + fkh);
            const float4* Kr = (const float4*)(K + ((size_t)b * S_ + si[frow]) * D_ + ck * 64 + fkh);
            #pragma unroll
            for (int i = 0; i < 8; ++i) {
                const int k = fkh + i * 4;
                const uint32_t off = frow * 128 + (((k >> 3) ^ (frow & 7)) * 16) + (k & 7) * 2;
                split_store4(AB + QHI_OFF, AB + QLO_OFF, off, Qr[i]);
                split_store4(AB + KHI_OFF, AB + KLO_OFF, off, Kr[i]);
            }
        }
        __syncthreads();
        const uint32_t arow = (w * 16 + lr) * 128;
        #pragma unroll
        for (int kk = 0; kk < 4; ++kk) {
            const uint32_t coff = (uint32_t)(((2 * kk + lc) ^ (lr & 7)) * 16);
            uint32_t ah0, ah1, ah2, ah3, al0, al1, al2, al3;
            LDSM4(ah0, ah1, ah2, ah3, ab + QHI_OFF + arow + coff);
            LDSM4(al0, al1, al2, al3, ab + QLO_OFF + arow + coff);
            #pragma unroll
            for (int np = 0; np < 8; ++np) {
                const uint32_t boff = (np * 16 + lr) * 128 + coff;
                uint32_t bh0, bh1, bh2, bh3, bl0, bl1, bl2, bl3;
                LDSM4(bh0, bh1, bh2, bh3, ab + KHI_OFF + boff);
                LDSM4(bl0, bl1, bl2, bl3, ab + KLO_OFF + boff);
                MMA(acc[2 * np],     ah0, ah1, ah2, ah3, bh0, bh2);
                MMA(acc[2 * np],     al0, al1, al2, al3, bh0, bh2);
                MMA(acc[2 * np],     ah0, ah1, ah2, ah3, bl0, bl2);
                MMA(acc[2 * np + 1], ah0, ah1, ah2, ah3, bh1, bh3);
                MMA(acc[2 * np + 1], al0, al1, al2, al3, bh1, bh3);
                MMA(acc[2 * np + 1], ah0, ah1, ah2, ah3, bl1, bl3);
            }
        }
        __syncthreads();
    }

    // ================= softmax in registers =================
    // lane holds rows (w*16 + rq) and (+8); cols j = nt*8 + 2*t4 + {0,1}
    {
        const int qa = w * 16 + rq;
        float mA = s128s[qa], mB = s128s[qa + 8];
        #pragma unroll
        for (int nt = 0; nt < 16; ++nt) {
            mA = fmaxf(mA, fmaxf(acc[nt][0], acc[nt][1]));
            mB = fmaxf(mB, fmaxf(acc[nt][2], acc[nt][3]));
        }
        mA = fmaxf(mA, __shfl_xor_sync(0xffffffffu, mA, 1));
        mA = fmaxf(mA, __shfl_xor_sync(0xffffffffu, mA, 2));
        mB = fmaxf(mB, __shfl_xor_sync(0xffffffffu, mB, 1));
        mB = fmaxf(mB, __shfl_xor_sync(0xffffffffu, mB, 2));

        float gA[NDEP], gB[NDEP];
        #pragma unroll
        for (int d = 0; d < NDEP; ++d) { gA[d] = 0.f; gB[d] = 0.f; }
        #pragma unroll
        for (int nt = 0; nt < 16; ++nt) {
            float e0 = __expf((acc[nt][0] - mA) * inv_scale);
            float e1 = __expf((acc[nt][1] - mA) * inv_scale);
            float e2 = __expf((acc[nt][2] - mB) * inv_scale);
            float e3 = __expf((acc[nt][3] - mB) * inv_scale);
            acc[nt][0] = e0; acc[nt][1] = e1; acc[nt][2] = e2; acc[nt][3] = e3;
            gacc(nt, gA, e0, e1, t4);
            gacc(nt, gB, e2, e3, t4);
        }
        // quad reduction FIRST...
        #pragma unroll
        for (int d = 0; d < NDEP; ++d) {
            gA[d] += __shfl_xor_sync(0xffffffffu, gA[d], 1);
            gA[d] += __shfl_xor_sync(0xffffffffu, gA[d], 2);
            gB[d] += __shfl_xor_sync(0xffffffffu, gB[d], 1);
            gB[d] += __shfl_xor_sync(0xffffffffu, gB[d], 2);
        }
        // ...THEN the (lane-uniform) j=128 term, added exactly once
        const float eA128 = __expf((s128s[qa] - mA) * inv_scale);
        const float eB128 = __expf((s128s[qa + 8] - mB) * inv_scale);
        gA[7] += eA128;
        gB[7] += eB128;

        float ZA = 0.f, ZB = 0.f, saA[NDEP], saB[NDEP];
        #pragma unroll
        for (int d = 0; d < NDEP; ++d) {
            ZA += gA[d]; saA[d] = __fdividef(wv[d], ZA);
            ZB += gB[d]; saB[d] = __fdividef(wv[d], ZB);
        }
        float sA = 0.f, sB = 0.f;
        #pragma unroll
        for (int d = NDEP - 1; d >= 0; --d) {
            sA += saA[d]; saA[d] = sA;
            sB += saB[d]; saB[d] = sB;
        }
        if (t4 == 0) {
            c128s[qa]     = eA128 * saA[7];
            c128s[qa + 8] = eB128 * saB[7];
        }
        // coefficients -> split-bf16 C tiles [q][j], pitch 272B
        #pragma unroll
        for (int nt = 0; nt < 16; ++nt) {
            float2 muA = samul(nt, saA, t4);
            float2 muB = samul(nt, saB, t4);
            uint32_t hi, lo;
            const uint32_t offc = (uint32_t)((nt * 8 + 2 * t4) * 2);
            split2(acc[nt][0] * muA.x, acc[nt][1] * muA.y, hi, lo);
            *(uint32_t*)(AB + CHI_OFF + qa * CPITCH + offc) = hi;
            *(uint32_t*)(AB + CLO_OFF + qa * CPITCH + offc) = lo;
            split2(acc[nt][2] * muB.x, acc[nt][3] * muB.y, hi, lo);
            *(uint32_t*)(AB + CHI_OFF + (qa + 8) * CPITCH + offc) = hi;
            *(uint32_t*)(AB + CLO_OFF + (qa + 8) * CPITCH + offc) = lo;
        }
    }
    __syncthreads();

    // ================= phase B: O = C . V^T  (8 d-chunks of 64) =================
    const int si128 = si[128];
    #pragma unroll 1
    for (int dc = 0; dc < 8; ++dc) {
        // fill Vt split tiles [d][j] pitch 272B
        {
            const int jp = tid & 63, dq = tid >> 6;
            const float* V0 = V + ((size_t)b * S_ + si[2 * jp]) * D_ + dc * 64 + dq * 16;
            const float* V1 = V + ((size_t)b * S_ + si[2 * jp + 1]) * D_ + dc * 64 + dq * 16;
            float4 r0[4], r1[4];
            #pragma unroll
            for (int i = 0; i < 4; ++i) { r0[i] = ((const float4*)V0)[i]; r1[i] = ((const float4*)V1)[i]; }
            #pragma unroll
            for (int dd = 0; dd < 16; ++dd) {
                const float c0 = ((const float*)r0)[dd];
                const float c1 = ((const float*)r1)[dd];
                uint32_t hi, lo;
                split2(c0, c1, hi, lo);
                const uint32_t off = (dq * 16 + dd) * CPITCH + jp * 4;
                *(uint32_t*)(AB + VHI_OFF + off) = hi;
                *(uint32_t*)(AB + VLO_OFF + off) = lo;
            }
        }
        __syncthreads();

        float oa[8][4];
        #pragma unroll
        for (int nt = 0; nt < 8; ++nt)
            #pragma unroll
            for (int i = 0; i < 4; ++i)
                oa[nt][i] = 0.f;

        #pragma unroll
        for (int kk = 0; kk < 8; ++kk) {
            const uint32_t aoff = (w * 16 + lr) * CPITCH + (2 * kk + lc) * 16;
            uint32_t ch0, ch1, ch2, ch3, cl0, cl1, cl2, cl3;
            LDSM4(ch0, ch1, ch2, ch3, ab + CHI_OFF + aoff);
            LDSM4(cl0, cl1, cl2, cl3, ab + CLO_OFF + aoff);
            #pragma unroll
            for (int np = 0; np < 4; ++np) {
                const uint32_t boff = (np * 16 + lr) * CPITCH + (2 * kk + lc) * 16;
                uint32_t vh0, vh1, vh2, vh3, vl0, vl1, vl2, vl3;
                LDSM4(vh0, vh1, vh2, vh3, ab + VHI_OFF + boff);
                LDSM4(vl0, vl1, vl2, vl3, ab + VLO_OFF + boff);
                MMA(oa[2 * np],     ch0, ch1, ch2, ch3, vh0, vh2);
                MMA(oa[2 * np],     cl0, cl1, cl2, cl3, vh0, vh2);
                MMA(oa[2 * np],     ch0, ch1, ch2, ch3, vl0, vl2);
                MMA(oa[2 * np + 1], ch0, ch1, ch2, ch3, vh1, vh3);
                MMA(oa[2 * np + 1], cl0, cl1, cl2, cl3, vh1, vh3);
                MMA(oa[2 * np + 1], ch0, ch1, ch2, ch3, vl1, vl3);
            }
        }

        // epilogue: add key-128 term, store O
        {
            const int qa = w * 16 + rq;
            const float cA = c128s[qa], cB = c128s[qa + 8];
            const float* v128 = V + ((size_t)b * S_ + si128) * D_ + dc * 64;
            float* OA = O + ((size_t)b * S_ + q0 + qa) * D_ + dc * 64;
            float* OB = OA + 8 * D_;
            #pragma unroll
            for (int nt = 0; nt < 8; ++nt) {
                const int nc = nt * 8 + 2 * t4;
                const float2 vv = *(const float2*)(v128 + nc);
                *(float2*)(OA + nc) = make_float2(oa[nt][0] + cA * vv.x, oa[nt][1] + cA * vv.y);
                *(float2*)(OB + nc) = make_float2(oa[nt][2] + cB * vv.x, oa[nt][3] + cB * vv.y);
            }
        }
        __syncthreads();
    }
}

// ---------------- launch ----------------
extern "C" void kernel_launch(void* const* d_in, const int* in_sizes, int n_in,
                              void* d_out, int out_size)
{
    const float* Q  = (const float*)d_in[0];
    const float* K  = (const float*)d_in[1];
    const float* V  = (const float*)d_in[2];
    // d_in[3] = t (unused by the reference)
    const float* SW = (const float*)d_in[4];
    const float* ST = (const float*)d_in[5];
    float* O = (float*)d_out;

    cudaFuncSetAttribute(ufa7_kernel, cudaFuncAttributeMaxDynamicSharedMemorySize, DYN_BYTES);

    dim3 grid(S_ / QT, B_);
    ufa7_kernel<<<grid, NTH, DYN_BYTES>>>(Q, K, V, SW, ST, O, g_tab);
}

// round 9
// speedup vs baseline: 1.9252x; 1.2982x over previous
#include <cuda_runtime.h>
#include <cuda_bf16.h>
#include <cstdint>
#include <vector>
#include <algorithm>

// ---------------- problem constants ----------------
#define B_    8
#define S_    4096
#define D_    512
#define QT    128
#define NTH   256
#define NDEP  8

// smem byte offsets (dynamic smem base AB)
// phase A tiles (128 rows x 128B, XOR-swizzled): 64KB
#define QHI_OFF 0
#define QLO_OFF 16384
#define KHI_OFF 32768
#define KLO_OFF 49152
// phase B: V tiles [128 j][72 bf16] pitch 144B, hi+lo, double buffered (overlays phase A)
#define VPITCH   144
#define VLO_REL  18432           // 128*144
#define VBUF_STR 36864           // hi+lo per buffer
#define DYN_BYTES 73728

// ---------------- host-side Cantor table (keys sorted by (dmin, idx)) ----------------
struct CTab { int idx[129]; };
static CTab g_tab;

static bool build_tables() {
    std::vector<std::vector<long long>> idxd;
    auto to_idx = [](const std::vector<double>& p) {
        std::vector<long long> v;
        for (double x : p) v.push_back((long long)(x * 4095.0));
        std::sort(v.begin(), v.end());
        v.erase(std::unique(v.begin(), v.end()), v.end());
        return v;
    };
    std::vector<double> prev = {0.0, 1.0};
    idxd.push_back(to_idx(prev));
    for (int d = 1; d < NDEP; ++d) {
        std::vector<double> nw;
        for (size_t i = 0; i + 1 < prev.size(); ++i) {
            double left = prev[i], right = prev[i + 1];
            double third = (right - left) / 3.0;
            nw.push_back(left);
            nw.push_back(left + third);
        }
        nw.push_back(prev.back());
        prev.swap(nw);
        idxd.push_back(to_idx(prev));
    }
    const std::vector<long long>& uni = idxd[NDEP - 1];   // 129 keys (nested union)
    int nu = (int)uni.size();
    std::vector<std::pair<int, long long>> keys;
    for (int j = 0; j < nu; ++j) {
        int dm = NDEP - 1;
        for (int d = 0; d < NDEP; ++d)
            if (std::binary_search(idxd[d].begin(), idxd[d].end(), uni[j])) { dm = d; break; }
        keys.push_back({dm, uni[j]});
    }
    std::sort(keys.begin(), keys.end());
    for (int j = 0; j < nu && j < 129; ++j) g_tab.idx[j] = (int)keys[j].second;
    return true;
}
static bool g_built = build_tables();
// sorted-slot depth groups: bnd = {0,2,3,5,9,17,33,65,129}

// ---------------- helpers ----------------
__device__ __forceinline__ uint32_t s2u(const void* p) {
    uint32_t a;
    asm("{ .reg .u64 t; cvta.to.shared.u64 t, %1; cvt.u32.u64 %0, t; }" : "=r"(a) : "l"(p));
    return a;
}

#define LDSM4(r0, r1, r2, r3, addr) \
    asm volatile("ldmatrix.sync.aligned.m8n8.x4.shared.b16 {%0,%1,%2,%3}, [%4];" \
                 : "=r"(r0), "=r"(r1), "=r"(r2), "=r"(r3) : "r"(addr))

#define LDSM4T(r0, r1, r2, r3, addr) \
    asm volatile("ldmatrix.sync.aligned.m8n8.x4.trans.shared.b16 {%0,%1,%2,%3}, [%4];" \
                 : "=r"(r0), "=r"(r1), "=r"(r2), "=r"(r3) : "r"(addr))

#define MMA(d, a0, a1, a2, a3, b0, b1) \
    asm volatile("mma.sync.aligned.m16n8k16.row.col.f32.bf16.bf16.f32 " \
                 "{%0,%1,%2,%3}, {%4,%5,%6,%7}, {%8,%9}, {%0,%1,%2,%3};" \
                 : "+f"((d)[0]), "+f"((d)[1]), "+f"((d)[2]), "+f"((d)[3]) \
                 : "r"(a0), "r"(a1), "r"(a2), "r"(a3), "r"(b0), "r"(b1))

// split x -> hi (round-to-nearest bf16) + lo (rounded bf16 of exact remainder); pack 2
__device__ __forceinline__ void split2(float c0, float c1, uint32_t& hi, uint32_t& lo) {
    asm("cvt.rn.bf16x2.f32 %0, %1, %2;" : "=r"(hi) : "f"(c1), "f"(c0));
    float h0 = __uint_as_float(hi << 16);
    float h1 = __uint_as_float(hi & 0xFFFF0000u);
    float l0 = c0 - h0;   // exact in fp32
    float l1 = c1 - h1;
    asm("cvt.rn.bf16x2.f32 %0, %1, %2;" : "=r"(lo) : "f"(l1), "f"(l0));
}
__device__ __forceinline__ void split_store4(char* hiB, char* loB, uint32_t off, float4 v) {
    uint32_t h01, l01, h23, l23;
    split2(v.x, v.y, h01, l01);
    split2(v.z, v.w, h23, l23);
    *(uint2*)(hiB + off) = make_uint2(h01, h23);
    *(uint2*)(loB + off) = make_uint2(l01, l23);
}

// depth-group accumulation (nt literal after unroll -> all indices static)
__device__ __forceinline__ void gacc(int nt, float* g, float e0, float e1, int t) {
    if (nt == 0) {
        g[0] += (t == 0) ? (e0 + e1) : 0.f;
        g[1] += (t == 1) ? e0 : 0.f;
        g[2] += (t == 1) ? e1 : ((t == 2) ? e0 : 0.f);
        g[3] += (t == 2) ? e1 : ((t == 3) ? (e0 + e1) : 0.f);
    } else if (nt == 1) {
        g[3] += (t == 0) ? e0 : 0.f;
        g[4] += (t == 0) ? e1 : (e0 + e1);
    } else if (nt == 2) {
        g[4] += (t == 0) ? e0 : 0.f;
        g[5] += (t == 0) ? e1 : (e0 + e1);
    } else if (nt == 3) {
        g[5] += e0 + e1;
    } else if (nt == 4) {
        g[5] += (t == 0) ? e0 : 0.f;
        g[6] += (t == 0) ? e1 : (e0 + e1);
    } else if (nt <= 7) {
        g[6] += e0 + e1;
    } else if (nt == 8) {
        g[6] += (t == 0) ? e0 : 0.f;
        g[7] += (t == 0) ? e1 : (e0 + e1);
    } else {
        g[7] += e0 + e1;
    }
}
__device__ __forceinline__ float2 samul(int nt, const float* sa, int t) {
    float m0, m1;
    if (nt == 0) {
        m0 = (t == 0) ? sa[0] : (t == 1) ? sa[1] : (t == 2) ? sa[2] : sa[3];
        m1 = (t == 0) ? sa[0] : (t == 1) ? sa[2] : sa[3];
    } else if (nt == 1) { m0 = (t == 0) ? sa[3] : sa[4]; m1 = sa[4]; }
    else if (nt == 2)   { m0 = (t == 0) ? sa[4] : sa[5]; m1 = sa[5]; }
    else if (nt == 3)   { m0 = sa[5]; m1 = sa[5]; }
    else if (nt == 4)   { m0 = (t == 0) ? sa[5] : sa[6]; m1 = sa[6]; }
    else if (nt <= 7)   { m0 = sa[6]; m1 = sa[6]; }
    else if (nt == 8)   { m0 = (t == 0) ? sa[6] : sa[7]; m1 = sa[7]; }
    else                { m0 = sa[7]; m1 = sa[7]; }
    return make_float2(m0, m1);
}

// ---------------- kernel ----------------
__global__ __launch_bounds__(NTH, 2)
void ufa8_kernel(const float* __restrict__ Q, const float* __restrict__ K,
                 const float* __restrict__ V, const float* __restrict__ SW,
                 const float* __restrict__ ST, float* __restrict__ O, CTab tab)
{
    extern __shared__ char AB[];
    const uint32_t ab = s2u(AB);

    __shared__ int   si[129];
    __shared__ float wv[NDEP];
    __shared__ float s128s[128];
    __shared__ float c128s[128];

    const int tid  = threadIdx.x;
    const int w    = tid >> 5;
    const int lane = tid & 31;
    const int b    = blockIdx.y;
    const int q0   = blockIdx.x * QT;
    const float inv_scale = 0.04419417382415922f;  // 1/sqrt(512)

    const int lr = lane & 15;   // ldmatrix row-within-16
    const int lc = lane >> 4;   // ldmatrix k-half
    const int t4 = lane & 3;
    const int rq = lane >> 2;   // fragment row 0..7

    for (int i = tid; i < 129; i += NTH) si[i] = tab.idx[i];
    if (tid == 0) {
        float tmp = ST[0];
        float vvv[NDEP];
        float m = -1e30f;
        #pragma unroll
        for (int d = 0; d < NDEP; ++d) { vvv[d] = SW[d] / tmp; m = fmaxf(m, vvv[d]); }
        float s = 0.f;
        #pragma unroll
        for (int d = 0; d < NDEP; ++d) { vvv[d] = __expf(vvv[d] - m); s += vvv[d]; }
        #pragma unroll
        for (int d = 0; d < NDEP; ++d) wv[d] = vvv[d] / s;
    }
    __syncthreads();

    // ---- raw score column j = 128 ----
    {
        int q = tid >> 1, h = tid & 1;
        const float4* qr = (const float4*)(Q + ((size_t)b * S_ + q0 + q) * D_ + h * 256);
        const float4* kr = (const float4*)(K + ((size_t)b * S_ + si[128]) * D_ + h * 256);
        float s = 0.f;
        #pragma unroll 8
        for (int i = 0; i < 64; ++i) {
            float4 a = qr[i], c = kr[i];
            s = fmaf(a.x, c.x, s); s = fmaf(a.y, c.y, s);
            s = fmaf(a.z, c.z, s); s = fmaf(a.w, c.w, s);
        }
        s += __shfl_xor_sync(0xffffffffu, s, 1);
        if (h == 0) s128s[q] = s;   // RAW (scaled later in softmax)
    }

    // ================= phase A: S = Q.K^T (raw), split-bf16 mma =================
    float acc[16][4];
    #pragma unroll
    for (int nt = 0; nt < 16; ++nt)
        #pragma unroll
        for (int i = 0; i < 4; ++i)
            acc[nt][i] = 0.f;

    const int frow = tid >> 1;
    const int fkh  = (tid & 1) * 32;

    #pragma unroll 1
    for (int ck = 0; ck < 8; ++ck) {
        // fill Q/K split tiles for this 64-dim chunk (128B rows, XOR-swizzled 16B chunks)
        {
            const float4* Qr = (const float4*)(Q + ((size_t)b * S_ + q0 + frow) * D_ + ck * 64 + fkh);
            const float4* Kr = (const float4*)(K + ((size_t)b * S_ + si[frow]) * D_ + ck * 64 + fkh);
            #pragma unroll
            for (int i = 0; i < 8; ++i) {
                const int k = fkh + i * 4;
                const uint32_t off = frow * 128 + (((k >> 3) ^ (frow & 7)) * 16) + (k & 7) * 2;
                split_store4(AB + QHI_OFF, AB + QLO_OFF, off, Qr[i]);
                split_store4(AB + KHI_OFF, AB + KLO_OFF, off, Kr[i]);
            }
        }
        __syncthreads();
        const uint32_t arow = (w * 16 + lr) * 128;
        #pragma unroll
        for (int kk = 0; kk < 4; ++kk) {
            const uint32_t coff = (uint32_t)(((2 * kk + lc) ^ (lr & 7)) * 16);
            uint32_t ah0, ah1, ah2, ah3, al0, al1, al2, al3;
            LDSM4(ah0, ah1, ah2, ah3, ab + QHI_OFF + arow + coff);
            LDSM4(al0, al1, al2, al3, ab + QLO_OFF + arow + coff);
            #pragma unroll
            for (int np = 0; np < 8; ++np) {
                const uint32_t boff = (np * 16 + lr) * 128 + coff;
                uint32_t bh0, bh1, bh2, bh3, bl0, bl1, bl2, bl3;
                LDSM4(bh0, bh1, bh2, bh3, ab + KHI_OFF + boff);
                LDSM4(bl0, bl1, bl2, bl3, ab + KLO_OFF + boff);
                MMA(acc[2 * np],     ah0, ah1, ah2, ah3, bh0, bh2);
                MMA(acc[2 * np],     al0, al1, al2, al3, bh0, bh2);
                MMA(acc[2 * np],     ah0, ah1, ah2, ah3, bl0, bl2);
                MMA(acc[2 * np + 1], ah0, ah1, ah2, ah3, bh1, bh3);
                MMA(acc[2 * np + 1], al0, al1, al2, al3, bh1, bh3);
                MMA(acc[2 * np + 1], ah0, ah1, ah2, ah3, bl1, bl3);
            }
        }
        __syncthreads();
    }

    // ================= softmax in registers -> C fragments in registers =================
    // lane holds rows (w*16 + rq) and (+8); cols j = nt*8 + 2*t4 + {0,1}
    uint32_t chi[8][4], clo[8][4];
    {
        const int qa = w * 16 + rq;
        float mA = s128s[qa], mB = s128s[qa + 8];
        #pragma unroll
        for (int nt = 0; nt < 16; ++nt) {
            mA = fmaxf(mA, fmaxf(acc[nt][0], acc[nt][1]));
            mB = fmaxf(mB, fmaxf(acc[nt][2], acc[nt][3]));
        }
        mA = fmaxf(mA, __shfl_xor_sync(0xffffffffu, mA, 1));
        mA = fmaxf(mA, __shfl_xor_sync(0xffffffffu, mA, 2));
        mB = fmaxf(mB, __shfl_xor_sync(0xffffffffu, mB, 1));
        mB = fmaxf(mB, __shfl_xor_sync(0xffffffffu, mB, 2));

        float gA[NDEP], gB[NDEP];
        #pragma unroll
        for (int d = 0; d < NDEP; ++d) { gA[d] = 0.f; gB[d] = 0.f; }
        #pragma unroll
        for (int nt = 0; nt < 16; ++nt) {
            float e0 = __expf((acc[nt][0] - mA) * inv_scale);
            float e1 = __expf((acc[nt][1] - mA) * inv_scale);
            float e2 = __expf((acc[nt][2] - mB) * inv_scale);
            float e3 = __expf((acc[nt][3] - mB) * inv_scale);
            acc[nt][0] = e0; acc[nt][1] = e1; acc[nt][2] = e2; acc[nt][3] = e3;
            gacc(nt, gA, e0, e1, t4);
            gacc(nt, gB, e2, e3, t4);
        }
        // quad reduction FIRST...
        #pragma unroll
        for (int d = 0; d < NDEP; ++d) {
            gA[d] += __shfl_xor_sync(0xffffffffu, gA[d], 1);
            gA[d] += __shfl_xor_sync(0xffffffffu, gA[d], 2);
            gB[d] += __shfl_xor_sync(0xffffffffu, gB[d], 1);
            gB[d] += __shfl_xor_sync(0xffffffffu, gB[d], 2);
        }
        // ...THEN the (lane-uniform) j=128 term, added exactly once
        const float eA128 = __expf((s128s[qa] - mA) * inv_scale);
        const float eB128 = __expf((s128s[qa + 8] - mB) * inv_scale);
        gA[7] += eA128;
        gB[7] += eB128;

        float ZA = 0.f, ZB = 0.f, saA[NDEP], saB[NDEP];
        #pragma unroll
        for (int d = 0; d < NDEP; ++d) {
            ZA += gA[d]; saA[d] = __fdividef(wv[d], ZA);
            ZB += gB[d]; saB[d] = __fdividef(wv[d], ZB);
        }
        float sA = 0.f, sB = 0.f;
        #pragma unroll
        for (int d = NDEP - 1; d >= 0; --d) {
            sA += saA[d]; saA[d] = sA;
            sB += saB[d]; saB[d] = sB;
        }
        if (t4 == 0) {
            c128s[qa]     = eA128 * saA[7];
            c128s[qa + 8] = eB128 * saB[7];
        }
        // coefficients -> mma A-fragment registers (acc layout == A-frag layout!)
        #pragma unroll
        for (int nt = 0; nt < 16; ++nt) {
            float2 muA = samul(nt, saA, t4);
            float2 muB = samul(nt, saB, t4);
            const int kk = nt >> 1;
            const int o  = (nt & 1) * 2;
            split2(acc[nt][0] * muA.x, acc[nt][1] * muA.y, chi[kk][o],     clo[kk][o]);
            split2(acc[nt][2] * muB.x, acc[nt][3] * muB.y, chi[kk][o + 1], clo[kk][o + 1]);
        }
    }

    // ================= phase B: O = C . V  (8 d-chunks of 64, double-buffered V) =================
    // V tiles stored row-major [j][d] (pitch 144B), consumed via ldmatrix.trans.
    auto fillV = [&](int dc, int s) {
        const int fj = tid >> 1;            // key row 0..127
        const int fh = tid & 1;             // 32-dim half
        char* vb = AB + s * VBUF_STR;
        const float4* Vr = (const float4*)(V + ((size_t)b * S_ + si[fj]) * D_ + dc * 64 + fh * 32);
        #pragma unroll
        for (int i = 0; i < 8; ++i) {
            float4 v = Vr[i];
            uint32_t h01, l01, h23, l23;
            split2(v.x, v.y, h01, l01);
            split2(v.z, v.w, h23, l23);
            const uint32_t off = fj * VPITCH + fh * 64 + i * 8;
            *(uint2*)(vb + off)           = make_uint2(h01, h23);
            *(uint2*)(vb + VLO_REL + off) = make_uint2(l01, l23);
        }
    };

    const int si128 = si[128];
    fillV(0, 0);
    __syncthreads();

    #pragma unroll 1
    for (int dc = 0; dc < 8; ++dc) {
        const int s = dc & 1;
        if (dc < 7) fillV(dc + 1, s ^ 1);

        float oa[8][4];
        #pragma unroll
        for (int nt = 0; nt < 8; ++nt)
            #pragma unroll
            for (int i = 0; i < 4; ++i)
                oa[nt][i] = 0.f;

        const uint32_t vbase = ab + s * VBUF_STR + (lane & 15) * VPITCH + (lane >> 4) * 16;
        #pragma unroll
        for (int kk = 0; kk < 8; ++kk) {
            #pragma unroll
            for (int ng = 0; ng < 4; ++ng) {
                const uint32_t a0 = vbase + kk * (16 * VPITCH) + ng * 32;
                uint32_t vh0, vh1, vh2, vh3, vl0, vl1, vl2, vl3;
                LDSM4T(vh0, vh1, vh2, vh3, a0);
                LDSM4T(vl0, vl1, vl2, vl3, a0 + VLO_REL);
                MMA(oa[2 * ng],     chi[kk][0], chi[kk][1], chi[kk][2], chi[kk][3], vh0, vh1);
                MMA(oa[2 * ng],     clo[kk][0], clo[kk][1], clo[kk][2], clo[kk][3], vh0, vh1);
                MMA(oa[2 * ng],     chi[kk][0], chi[kk][1], chi[kk][2], chi[kk][3], vl0, vl1);
                MMA(oa[2 * ng + 1], chi[kk][0], chi[kk][1], chi[kk][2], chi[kk][3], vh2, vh3);
                MMA(oa[2 * ng + 1], clo[kk][0], clo[kk][1], clo[kk][2], clo[kk][3], vh2, vh3);
                MMA(oa[2 * ng + 1], chi[kk][0], chi[kk][1], chi[kk][2], chi[kk][3], vl2, vl3);
            }
        }

        // epilogue: add key-128 term, store O
        {
            const int qa = w * 16 + rq;
            const float cA = c128s[qa], cB = c128s[qa + 8];
            const float* v128 = V + ((size_t)b * S_ + si128) * D_ + dc * 64;
            float* OA = O + ((size_t)b * S_ + q0 + qa) * D_ + dc * 64;
            float* OB = OA + 8 * D_;
            #pragma unroll
            for (int nt = 0; nt < 8; ++nt) {
                const int nc = nt * 8 + 2 * t4;
                const float2 vv = *(const float2*)(v128 + nc);
                *(float2*)(OA + nc) = make_float2(oa[nt][0] + cA * vv.x, oa[nt][1] + cA * vv.y);
                *(float2*)(OB + nc) = make_float2(oa[nt][2] + cB * vv.x, oa[nt][3] + cB * vv.y);
            }
        }
        __syncthreads();
    }
}

// ---------------- launch ----------------
extern "C" void kernel_launch(void* const* d_in, const int* in_sizes, int n_in,
                              void* d_out, int out_size)
{
    const float* Q  = (const float*)d_in[0];
    const float* K  = (const float*)d_in[1];
    const float* V  = (const float*)d_in[2];
    // d_in[3] = t (unused by the reference)
    const float* SW = (const float*)d_in[4];
    const float* ST = (const float*)d_in[5];
    float* O = (float*)d_out;

    cudaFuncSetAttribute(ufa8_kernel, cudaFuncAttributeMaxDynamicSharedMemorySize, DYN_BYTES);

    dim3 grid(S_ / QT, B_);
    ufa8_kernel<<<grid, NTH, DYN_BYTES>>>(Q, K, V, SW, ST, O, g_tab);
}